// round 12
// baseline (speedup 1.0000x reference)
#include <cuda_runtime.h>
#include <cuda_fp16.h>
#include <math.h>
#include <stdint.h>

// ---------------- problem constants ----------------
#define TOK   8192
#define HDIM  1024
#define NEXP  8
#define FDIM  4096
#define NSLOT (TOK*2)

// ---------------- device scratch ----------------
__device__ int   g_count[NEXP];
__device__ int   g_cursor[NEXP];
__device__ int   g_exp[TOK * 2];
__device__ float g_wt[TOK * 2];
__device__ int   g_tok_slot[NSLOT];
__device__ float g_wt_slot[NSLOT];

// fp16 operands (K-major rows). +128 row pad so OOB tile reads stay in-bounds.
__device__ __half g_a1[(size_t)(NSLOT + 128) * HDIM];
__device__ __half g_b1[(size_t)NEXP * FDIM * HDIM];              // [E][N][K]
__device__ __half g_a2[(size_t)(NSLOT + 128) * FDIM];
__device__ __half g_b2[(size_t)NEXP * HDIM * FDIM];              // [E][N][K]

// ---------------- helpers ----------------
__device__ __forceinline__ uint32_t smem_u32(const void* p) {
    return (uint32_t)__cvta_generic_to_shared(p);
}
__device__ __forceinline__ void cp_async16(uint32_t dst, const void* src) {
    asm volatile("cp.async.cg.shared.global [%0], [%1], 16;" :: "r"(dst), "l"(src) : "memory");
}
__device__ __forceinline__ void cp_commit() {
    asm volatile("cp.async.commit_group;" ::: "memory");
}
template <int N>
__device__ __forceinline__ void cp_wait() {
    asm volatile("cp.async.wait_group %0;" :: "n"(N) : "memory");
}
__device__ __forceinline__ void mbar_arrive(uint32_t mbar) {
    asm volatile("mbarrier.arrive.release.cta.shared::cta.b64 _, [%0];" :: "r"(mbar) : "memory");
}
#define MBARRIER_INIT(addr, cnt) \
    asm volatile("mbarrier.init.shared.b64 [%0], %1;" :: "r"(addr), "r"(cnt) : "memory")

#define MBARRIER_WAIT_PARITY(mbar_smem_addr, phase_parity) do { \
    uint32_t _mbar = (uint32_t)(mbar_smem_addr); \
    uint32_t _parity = (uint32_t)(phase_parity); \
    uint32_t _done; \
    asm volatile( \
        "{\n\t.reg .pred p;\n\t" \
        "mbarrier.try_wait.parity.acquire.cta.shared::cta.b64 p, [%1], %2;\n\t" \
        "selp.b32 %0, 1, 0, p;\n\t}" \
        : "=r"(_done) : "r"(_mbar), "r"(_parity) : "memory"); \
    if (!_done) { \
        asm volatile( \
            "{\n\t.reg .pred P1;\n\t" \
            "WAIT_LOOP_%=:\n\t" \
            "mbarrier.try_wait.parity.acquire.cta.shared::cta.b64 P1, [%0], %1, 0x989680;\n\t" \
            "@P1 bra.uni WAIT_DONE_%=;\n\t" \
            "bra.uni WAIT_LOOP_%=;\n\t" \
            "WAIT_DONE_%=:\n\t}" \
            :: "r"(_mbar), "r"(_parity) : "memory"); \
    } \
} while (0)

__device__ __forceinline__ void ldsm_x4(uint32_t* r, uint32_t addr) {
    asm volatile("ldmatrix.sync.aligned.m8n8.x4.shared.b16 {%0,%1,%2,%3}, [%4];"
                 : "=r"(r[0]), "=r"(r[1]), "=r"(r[2]), "=r"(r[3]) : "r"(addr));
}
__device__ __forceinline__ void mma_fp16(float* c, const uint32_t* a, uint32_t b0, uint32_t b1) {
    asm volatile(
        "mma.sync.aligned.m16n8k16.row.col.f32.f16.f16.f32 "
        "{%0,%1,%2,%3}, {%4,%5,%6,%7}, {%8,%9}, {%0,%1,%2,%3};"
        : "+f"(c[0]), "+f"(c[1]), "+f"(c[2]), "+f"(c[3])
        : "r"(a[0]), "r"(a[1]), "r"(a[2]), "r"(a[3]), "r"(b0), "r"(b1));
}
__device__ __forceinline__ float gelu_exact(float v) {
    return 0.5f * v * (1.0f + erff(v * 0.70710678118654752f));
}

// ---------------- router ----------------
__global__ void router_kernel(const float* __restrict__ x,
                              const float* __restrict__ rw,
                              const float* __restrict__ rb) {
    int t = blockIdx.x * 8 + threadIdx.y;
    if (t >= TOK) return;
    int lane = threadIdx.x;
    float acc[8];
#pragma unroll
    for (int e = 0; e < 8; e++) acc[e] = 0.f;
    const float* xr = x + (size_t)t * HDIM;
    for (int h = lane; h < HDIM; h += 32) {
        float xv = xr[h];
        const float4 w0 = *(const float4*)(rw + h * 8);
        const float4 w1 = *(const float4*)(rw + h * 8 + 4);
        acc[0] += xv * w0.x; acc[1] += xv * w0.y;
        acc[2] += xv * w0.z; acc[3] += xv * w0.w;
        acc[4] += xv * w1.x; acc[5] += xv * w1.y;
        acc[6] += xv * w1.z; acc[7] += xv * w1.w;
    }
#pragma unroll
    for (int off = 16; off > 0; off >>= 1)
#pragma unroll
        for (int e = 0; e < 8; e++)
            acc[e] += __shfl_down_sync(0xffffffffu, acc[e], off);
    if (lane == 0) {
        float l[8];
#pragma unroll
        for (int e = 0; e < 8; e++) l[e] = acc[e] + rb[e];
        float mx = l[0];
#pragma unroll
        for (int e = 1; e < 8; e++) mx = fmaxf(mx, l[e]);
        float p[8];
#pragma unroll
        for (int e = 0; e < 8; e++) p[e] = __expf(l[e] - mx);
        int e1 = 0; float p1 = p[0];
#pragma unroll
        for (int e = 1; e < 8; e++) if (p[e] > p1) { p1 = p[e]; e1 = e; }
        int e2 = -1; float p2 = -1.f;
#pragma unroll
        for (int e = 0; e < 8; e++) if (e != e1 && p[e] > p2) { p2 = p[e]; e2 = e; }
        float inv = 1.f / (p1 + p2);
        g_exp[t * 2 + 0] = e1; g_wt[t * 2 + 0] = p1 * inv;
        g_exp[t * 2 + 1] = e2; g_wt[t * 2 + 1] = p2 * inv;
        atomicAdd(&g_count[e1], 1);
        atomicAdd(&g_count[e2], 1);
    }
}

// scatter with inline 8-expert prefix
__global__ void scatter_kernel() {
    int t = blockIdx.x * blockDim.x + threadIdx.x;
    if (t >= TOK) return;
    int offs[NEXP];
    int o = 0;
#pragma unroll
    for (int e = 0; e < NEXP; e++) { offs[e] = o; o += g_count[e]; }
#pragma unroll
    for (int k = 0; k < 2; k++) {
        int e = g_exp[t * 2 + k];
        float w = g_wt[t * 2 + k];
        int pos = atomicAdd(&g_cursor[e], 1);
        int slot = offs[e] + pos;
        g_tok_slot[slot] = t;
        g_wt_slot[slot] = w;
    }
}

// ---------------- fused conversion kernel ----------------
#define CVX_BLKS  8192
#define CVW1_BLKS 32768
#define CVW2_BLKS 32768
#define CONV_BLKS (CVX_BLKS + CVW1_BLKS + CVW2_BLKS)

__global__ void conv_all(const float* __restrict__ x,
                         const float* __restrict__ w1,
                         const float* __restrict__ w2) {
    __shared__ float tile[32][33];
    int b = blockIdx.x;
    int t = threadIdx.x;   // 256
    if (b < CVX_BLKS) {
        int slot = b * 2 + (t >> 7);
        int tt = t & 127;
        int tok = g_tok_slot[slot];
        const float4* xr = (const float4*)(x + (size_t)tok * HDIM);
        __half2* dst = (__half2*)(g_a1 + (size_t)slot * HDIM);
        for (int i = tt; i < 256; i += 128) {
            float4 v = xr[i];
            dst[2 * i]     = __floats2half2_rn(v.x, v.y);
            dst[2 * i + 1] = __floats2half2_rn(v.z, v.w);
        }
        return;
    }
    const float* w; __half* Bp; int K, N, idx;
    if (b < CVX_BLKS + CVW1_BLKS) { w = w1; Bp = g_b1; K = HDIM; N = FDIM; idx = b - CVX_BLKS; }
    else                          { w = w2; Bp = g_b2; K = FDIM; N = HDIM; idx = b - CVX_BLKS - CVW1_BLKS; }
    int nx = N / 32;
    int per_e = nx * (K / 32);
    int e = idx / per_e;
    int rem = idx % per_e;
    int n0 = (rem % nx) * 32, k0 = (rem / nx) * 32;
    int tx = t & 31, ty = t >> 5;
    const float* we = w + (size_t)e * K * N;
    __half* Be = Bp + (size_t)e * N * K;
#pragma unroll
    for (int r = 0; r < 32; r += 8)
        tile[ty + r][tx] = we[(size_t)(k0 + ty + r) * N + n0 + tx];
    __syncthreads();
#pragma unroll
    for (int r = 0; r < 32; r += 8) {
        int n = n0 + ty + r, k = k0 + tx;
        Be[(size_t)n * K + k] = __float2half_rn(tile[tx][ty + r]);
    }
}

// ---------------- warp-specialized mma.sync GEMM ----------------
// 288 threads: warps 0-7 consumers (2x4, 64x64 warp tiles over 128x256 CTA
// tile), warp 8 producer. Stage = 64 K-elements (two 32-wide subchunks,
// [A0|B0|A1|B1]); ONE full-wait + ONE empty-arrive per 64 K. 3 stages.
#define ROWB 80
#define A_TILEB (128 * ROWB)
#define B_TILEB (256 * ROWB)
#define SUBB    (A_TILEB + B_TILEB)   // 30720 per 32-wide subchunk
#define STAGEB  (2 * SUBB)            // 61440 per stage (64 K)
#define STAGES 3
#define BAR_OFF (STAGES * STAGEB)
#define SMEM_DYN (BAR_OFF + STAGES * 16)   // 184368
#define NTHR 288
#define PROD_WID 8

template <int KD>
__device__ __forceinline__ void mma_mainloop(
    const __half* __restrict__ Aseg,   // 128 rows, stride KD
    const __half* __restrict__ Bseg,   // 256 rows, stride KD
    char* smb, float c[4][8][4], int tid, int lane, int wid, int wm, int wn)
{
    const int NCH = KD / 64;           // 64-wide chunks

    uint32_t smbase = smem_u32(smb);
    uint32_t sg[STAGES];
#pragma unroll
    for (int s = 0; s < STAGES; s++) sg[s] = smbase + s * STAGEB;
    uint32_t barb = smbase + BAR_OFF;  // full[s]=+s*16, empty[s]=+s*16+8

    if (tid == 0) {
#pragma unroll
        for (int s = 0; s < STAGES; s++) {
            MBARRIER_INIT(barb + s * 16, 32);       // full: producer lanes
            MBARRIER_INIT(barb + s * 16 + 8, 256);  // empty: consumer threads
        }
    }
    __syncthreads();

    if (wid == PROD_WID) {
        // ---------------- producer warp ----------------
        auto p_issue = [&](int ci, int s) {
#pragma unroll
            for (int sub = 0; sub < 2; sub++) {
                int koff = (ci * 2 + sub) * 32;
                uint32_t sav = sg[s] + sub * SUBB;
                uint32_t sbv = sav + A_TILEB;
#pragma unroll
                for (int i = 0; i < 16; i++) {
                    int u = lane + 32 * i;
                    int r = u >> 2, cu = u & 3;
                    cp_async16(sav + r * ROWB + cu * 16,
                               Aseg + (size_t)r * KD + koff + cu * 8);
                }
#pragma unroll
                for (int i = 0; i < 32; i++) {
                    int u = lane + 32 * i;
                    int r = u >> 2, cu = u & 3;
                    cp_async16(sbv + r * ROWB + cu * 16,
                               Bseg + (size_t)r * KD + koff + cu * 8);
                }
            }
            cp_commit();
        };

        int pst = 0, pph = 1;
        for (int ci = 0; ci < NCH; ci++) {
            MBARRIER_WAIT_PARITY(barb + pst * 16 + 8, pph);
            p_issue(ci, pst);
            if (++pst == STAGES) { pst = 0; pph ^= 1; }
            if (ci >= 2) {
                cp_wait<2>();                              // group ci-2 done
                mbar_arrive(barb + ((ci - 2) % STAGES) * 16);
            }
        }
        cp_wait<1>();
        mbar_arrive(barb + ((NCH - 2) % STAGES) * 16);
        cp_wait<0>();
        mbar_arrive(barb + ((NCH - 1) % STAGES) * 16);
    } else {
        // ---------------- consumer warps (64x64 warp tile) ----------------
        uint32_t a_off = (uint32_t)((wm * 64 + (lane & 15)) * ROWB + (lane >> 4) * 16);
        int bn = (lane & 7) + ((lane & 16) >> 1);
        uint32_t b_off = (uint32_t)((wn * 64 + bn) * ROWB + ((lane >> 3) & 1) * 16);

        int cst = 0, cph = 0;
        for (int ci = 0; ci < NCH; ci++) {
            MBARRIER_WAIT_PARITY(barb + cst * 16, cph);    // one wait per 64 K
#pragma unroll
            for (int sub = 0; sub < 2; sub++) {
                uint32_t sav = sg[cst] + sub * SUBB;
                uint32_t sbv = sav + A_TILEB;

                uint32_t a[2][4][4], b[2][4][4];
#pragma unroll
                for (int ks = 0; ks < 2; ks++) {
#pragma unroll
                    for (int mt = 0; mt < 4; mt++)
                        ldsm_x4(a[ks][mt], sav + a_off + mt * (16 * ROWB) + ks * 32);
#pragma unroll
                    for (int nt = 0; nt < 4; nt++)
                        ldsm_x4(b[ks][nt], sbv + b_off + nt * (16 * ROWB) + ks * 32);
                }
                if (sub == 1) mbar_arrive(barb + cst * 16 + 8);  // all reads done
#pragma unroll
                for (int ks = 0; ks < 2; ks++) {
#pragma unroll
                    for (int mt = 0; mt < 4; mt++) {
#pragma unroll
                        for (int j = 0; j < 8; j++)
                            mma_fp16(c[mt][j], a[ks][mt],
                                     b[ks][j >> 1][(j & 1) * 2], b[ks][j >> 1][(j & 1) * 2 + 1]);
                    }
                }
            }
            if (++cst == STAGES) { cst = 0; cph ^= 1; }
        }
    }
}

__global__ void __launch_bounds__(NTHR, 1)
gemm1_mma(const float* __restrict__ b1) {
    const int e = blockIdx.z;
    const int cnt = g_count[e];
    const int m0 = blockIdx.y * 128;
    if (m0 >= cnt) return;
    const int n0 = blockIdx.x * 256;
    int seg = 0;
    {
        int o = 0;
#pragma unroll
        for (int ee = 0; ee < NEXP; ee++) { if (ee == e) seg = o; o += g_count[ee]; }
    }

    extern __shared__ char smb[];
    int tid = threadIdx.x, lane = tid & 31, wid = tid >> 5;
    int wm = wid & 1, wn = wid >> 1;   // consumers: wn 0..3

    const __half* Aseg = g_a1 + (size_t)(seg + m0) * HDIM;
    const __half* Bseg = g_b1 + ((size_t)e * FDIM + n0) * HDIM;

    float c[4][8][4];
#pragma unroll
    for (int i = 0; i < 4; i++)
#pragma unroll
        for (int j = 0; j < 8; j++)
#pragma unroll
            for (int k = 0; k < 4; k++) c[i][j][k] = 0.f;

    mma_mainloop<HDIM>(Aseg, Bseg, smb, c, tid, lane, wid, wm, wn);
    if (wid == PROD_WID) return;

    // epilogue: gelu(acc + b1) -> fp16 -> g_a2
    int n_base = n0 + wn * 64 + (lane & 3) * 2;
    int m_base = m0 + wm * 64 + (lane >> 2);
#pragma unroll
    for (int mt = 0; mt < 4; mt++) {
#pragma unroll
        for (int half = 0; half < 2; half++) {
            int m = m_base + mt * 16 + half * 8;
            if (m >= cnt) continue;
            __half* rowp = g_a2 + (size_t)(seg + m) * FDIM;
#pragma unroll
            for (int j = 0; j < 8; j++) {
                int n = n_base + j * 8;
                float2 bv = *(const float2*)(b1 + e * FDIM + n);
                float g0 = gelu_exact(c[mt][j][half * 2 + 0] + bv.x);
                float g1 = gelu_exact(c[mt][j][half * 2 + 1] + bv.y);
                *(__half2*)(rowp + n) = __floats2half2_rn(g0, g1);
            }
        }
    }
}

__global__ void __launch_bounds__(NTHR, 1)
gemm2_mma(const float* __restrict__ b2, float* __restrict__ out) {
    const int e = blockIdx.z;
    const int cnt = g_count[e];
    const int m0 = blockIdx.y * 128;
    if (m0 >= cnt) return;
    const int n0 = blockIdx.x * 256;
    int seg = 0;
    {
        int o = 0;
#pragma unroll
        for (int ee = 0; ee < NEXP; ee++) { if (ee == e) seg = o; o += g_count[ee]; }
    }

    extern __shared__ char smb[];
    int tid = threadIdx.x, lane = tid & 31, wid = tid >> 5;
    int wm = wid & 1, wn = wid >> 1;

    const __half* Aseg = g_a2 + (size_t)(seg + m0) * FDIM;
    const __half* Bseg = g_b2 + ((size_t)e * HDIM + n0) * FDIM;

    float c[4][8][4];
#pragma unroll
    for (int i = 0; i < 4; i++)
#pragma unroll
        for (int j = 0; j < 8; j++)
#pragma unroll
            for (int k = 0; k < 4; k++) c[i][j][k] = 0.f;

    mma_mainloop<FDIM>(Aseg, Bseg, smb, c, tid, lane, wid, wm, wn);
    if (wid == PROD_WID) return;

    // epilogue: out[tok] += wt * (acc + b2)
    int n_base = n0 + wn * 64 + (lane & 3) * 2;
    int m_base = m0 + wm * 64 + (lane >> 2);
#pragma unroll
    for (int mt = 0; mt < 4; mt++) {
#pragma unroll
        for (int half = 0; half < 2; half++) {
            int m = m_base + mt * 16 + half * 8;
            if (m >= cnt) continue;
            int t = g_tok_slot[seg + m];
            float wt = g_wt_slot[seg + m];
            float* orow = out + (size_t)t * HDIM;
#pragma unroll
            for (int j = 0; j < 8; j++) {
                int n = n_base + j * 8;
                float2 bv = *(const float2*)(b2 + e * HDIM + n);
                atomicAdd(&orow[n],     wt * (c[mt][j][half * 2 + 0] + bv.x));
                atomicAdd(&orow[n + 1], wt * (c[mt][j][half * 2 + 1] + bv.y));
            }
        }
    }
}

// ---------------- launch ----------------
extern "C" void kernel_launch(void* const* d_in, const int* in_sizes, int n_in,
                              void* d_out, int out_size) {
    const float* x  = (const float*)d_in[0];
    const float* rw = (const float*)d_in[1];
    const float* rb = (const float*)d_in[2];
    const float* w1 = (const float*)d_in[3];
    const float* b1 = (const float*)d_in[4];
    const float* w2 = (const float*)d_in[5];
    const float* b2 = (const float*)d_in[6];
    float* out = (float*)d_out;

    cudaFuncSetAttribute(gemm1_mma, cudaFuncAttributeMaxDynamicSharedMemorySize, SMEM_DYN);
    cudaFuncSetAttribute(gemm2_mma, cudaFuncAttributeMaxDynamicSharedMemorySize, SMEM_DYN);

    int* cntp; cudaGetSymbolAddress((void**)&cntp, g_count);
    int* curp; cudaGetSymbolAddress((void**)&curp, g_cursor);

    cudaMemsetAsync(out, 0, (size_t)out_size * sizeof(float));
    cudaMemsetAsync(cntp, 0, NEXP * sizeof(int));
    cudaMemsetAsync(curp, 0, NEXP * sizeof(int));

    router_kernel<<<TOK / 8, dim3(32, 8)>>>(x, rw, rb);          // launch 0
    scatter_kernel<<<TOK / 256, 256>>>();                        // launch 1
    conv_all<<<CONV_BLKS, 256>>>(x, w1, w2);                     // launch 2
    gemm1_mma<<<dim3(FDIM / 256, TOK / 128, NEXP), NTHR, SMEM_DYN>>>(b1);       // launch 3
    gemm2_mma<<<dim3(HDIM / 256, TOK / 128, NEXP), NTHR, SMEM_DYN>>>(b2, out);  // launch 4
}

// round 13
// speedup vs baseline: 1.1694x; 1.1694x over previous
#include <cuda_runtime.h>
#include <cuda_fp16.h>
#include <math.h>
#include <stdint.h>

// ---------------- problem constants ----------------
#define TOK   8192
#define HDIM  1024
#define NEXP  8
#define FDIM  4096
#define NSLOT (TOK*2)

// ---------------- device scratch ----------------
__device__ int   g_count[NEXP];
__device__ int   g_cursor[NEXP];
__device__ int   g_exp[TOK * 2];
__device__ float g_wt[TOK * 2];
__device__ int   g_tok_slot[NSLOT + 128];   // +128 zeroed pad for OOB tile rows
__device__ float g_wt_slot[NSLOT];

// fp16 operands. g_x16 is TOKEN-ordered (written by router); A1 is gathered
// through g_tok_slot by gemm1's producer. g_a2 stays slot-ordered.
__device__ __half g_x16[(size_t)TOK * HDIM];
__device__ __half g_b1[(size_t)NEXP * FDIM * HDIM];              // [E][N][K]
__device__ __half g_a2[(size_t)(NSLOT + 128) * FDIM];
__device__ __half g_b2[(size_t)NEXP * HDIM * FDIM];              // [E][N][K]

// ---------------- helpers ----------------
__device__ __forceinline__ uint32_t smem_u32(const void* p) {
    return (uint32_t)__cvta_generic_to_shared(p);
}
__device__ __forceinline__ void cp_async16(uint32_t dst, const void* src) {
    asm volatile("cp.async.cg.shared.global [%0], [%1], 16;" :: "r"(dst), "l"(src) : "memory");
}
__device__ __forceinline__ void cp_commit() {
    asm volatile("cp.async.commit_group;" ::: "memory");
}
template <int N>
__device__ __forceinline__ void cp_wait() {
    asm volatile("cp.async.wait_group %0;" :: "n"(N) : "memory");
}
__device__ __forceinline__ void mbar_arrive(uint32_t mbar) {
    asm volatile("mbarrier.arrive.release.cta.shared::cta.b64 _, [%0];" :: "r"(mbar) : "memory");
}
#define MBARRIER_INIT(addr, cnt) \
    asm volatile("mbarrier.init.shared.b64 [%0], %1;" :: "r"(addr), "r"(cnt) : "memory")

#define MBARRIER_WAIT_PARITY(mbar_smem_addr, phase_parity) do { \
    uint32_t _mbar = (uint32_t)(mbar_smem_addr); \
    uint32_t _parity = (uint32_t)(phase_parity); \
    uint32_t _done; \
    asm volatile( \
        "{\n\t.reg .pred p;\n\t" \
        "mbarrier.try_wait.parity.acquire.cta.shared::cta.b64 p, [%1], %2;\n\t" \
        "selp.b32 %0, 1, 0, p;\n\t}" \
        : "=r"(_done) : "r"(_mbar), "r"(_parity) : "memory"); \
    if (!_done) { \
        asm volatile( \
            "{\n\t.reg .pred P1;\n\t" \
            "WAIT_LOOP_%=:\n\t" \
            "mbarrier.try_wait.parity.acquire.cta.shared::cta.b64 P1, [%0], %1, 0x989680;\n\t" \
            "@P1 bra.uni WAIT_DONE_%=;\n\t" \
            "bra.uni WAIT_LOOP_%=;\n\t" \
            "WAIT_DONE_%=:\n\t}" \
            :: "r"(_mbar), "r"(_parity) : "memory"); \
    } \
} while (0)

__device__ __forceinline__ void ldsm_x4(uint32_t* r, uint32_t addr) {
    asm volatile("ldmatrix.sync.aligned.m8n8.x4.shared.b16 {%0,%1,%2,%3}, [%4];"
                 : "=r"(r[0]), "=r"(r[1]), "=r"(r[2]), "=r"(r[3]) : "r"(addr));
}
__device__ __forceinline__ void mma_fp16(float* c, const uint32_t* a, uint32_t b0, uint32_t b1) {
    asm volatile(
        "mma.sync.aligned.m16n8k16.row.col.f32.f16.f16.f32 "
        "{%0,%1,%2,%3}, {%4,%5,%6,%7}, {%8,%9}, {%0,%1,%2,%3};"
        : "+f"(c[0]), "+f"(c[1]), "+f"(c[2]), "+f"(c[3])
        : "r"(a[0]), "r"(a[1]), "r"(a[2]), "r"(a[3]), "r"(b0), "r"(b1));
}
__device__ __forceinline__ float gelu_exact(float v) {
    return 0.5f * v * (1.0f + erff(v * 0.70710678118654752f));
}

// ---------------- router (also converts x -> fp16, token order) ----------------
__global__ void router_kernel(const float* __restrict__ x,
                              const float* __restrict__ rw,
                              const float* __restrict__ rb) {
    int t = blockIdx.x * 8 + threadIdx.y;
    if (t >= TOK) return;
    int lane = threadIdx.x;
    float acc[8];
#pragma unroll
    for (int e = 0; e < 8; e++) acc[e] = 0.f;
    const float* xr = x + (size_t)t * HDIM;
    __half* x16r = g_x16 + (size_t)t * HDIM;
    for (int h = lane; h < HDIM; h += 32) {
        float xv = xr[h];
        x16r[h] = __float2half_rn(xv);           // fused fp16 conversion
        const float4 w0 = *(const float4*)(rw + h * 8);
        const float4 w1 = *(const float4*)(rw + h * 8 + 4);
        acc[0] += xv * w0.x; acc[1] += xv * w0.y;
        acc[2] += xv * w0.z; acc[3] += xv * w0.w;
        acc[4] += xv * w1.x; acc[5] += xv * w1.y;
        acc[6] += xv * w1.z; acc[7] += xv * w1.w;
    }
#pragma unroll
    for (int off = 16; off > 0; off >>= 1)
#pragma unroll
        for (int e = 0; e < 8; e++)
            acc[e] += __shfl_down_sync(0xffffffffu, acc[e], off);
    if (lane == 0) {
        float l[8];
#pragma unroll
        for (int e = 0; e < 8; e++) l[e] = acc[e] + rb[e];
        float mx = l[0];
#pragma unroll
        for (int e = 1; e < 8; e++) mx = fmaxf(mx, l[e]);
        float p[8];
#pragma unroll
        for (int e = 0; e < 8; e++) p[e] = __expf(l[e] - mx);
        int e1 = 0; float p1 = p[0];
#pragma unroll
        for (int e = 1; e < 8; e++) if (p[e] > p1) { p1 = p[e]; e1 = e; }
        int e2 = -1; float p2 = -1.f;
#pragma unroll
        for (int e = 0; e < 8; e++) if (e != e1 && p[e] > p2) { p2 = p[e]; e2 = e; }
        float inv = 1.f / (p1 + p2);
        g_exp[t * 2 + 0] = e1; g_wt[t * 2 + 0] = p1 * inv;
        g_exp[t * 2 + 1] = e2; g_wt[t * 2 + 1] = p2 * inv;
        atomicAdd(&g_count[e1], 1);
        atomicAdd(&g_count[e2], 1);
    }
}

// scatter with inline 8-expert prefix; also zeroes the tok_slot pad
__global__ void scatter_kernel() {
    int t = blockIdx.x * blockDim.x + threadIdx.x;
    if (t < 128) g_tok_slot[NSLOT + t] = 0;
    if (t >= TOK) return;
    int offs[NEXP];
    int o = 0;
#pragma unroll
    for (int e = 0; e < NEXP; e++) { offs[e] = o; o += g_count[e]; }
#pragma unroll
    for (int k = 0; k < 2; k++) {
        int e = g_exp[t * 2 + k];
        float w = g_wt[t * 2 + k];
        int pos = atomicAdd(&g_cursor[e], 1);
        int slot = offs[e] + pos;
        g_tok_slot[slot] = t;
        g_wt_slot[slot] = w;
    }
}

// ---------------- w1 conversion kernel (w2 is converted inside gemm1) ------
#define CVW1_BLKS 32768
__global__ void conv_w1(const float* __restrict__ w1) {
    __shared__ float tile[32][33];
    int idx = blockIdx.x;
    int t = threadIdx.x;   // 256
    const int K = HDIM, N = FDIM;
    int nx = N / 32;
    int per_e = nx * (K / 32);
    int e = idx / per_e;
    int rem = idx % per_e;
    int n0 = (rem % nx) * 32, k0 = (rem / nx) * 32;
    int tx = t & 31, ty = t >> 5;
    const float* we = w1 + (size_t)e * K * N;
    __half* Be = g_b1 + (size_t)e * N * K;
#pragma unroll
    for (int r = 0; r < 32; r += 8)
        tile[ty + r][tx] = we[(size_t)(k0 + ty + r) * N + n0 + tx];
    __syncthreads();
#pragma unroll
    for (int r = 0; r < 32; r += 8) {
        int n = n0 + ty + r, k = k0 + tx;
        Be[(size_t)n * K + k] = __float2half_rn(tile[tx][ty + r]);
    }
}

// ---------------- warp-specialized mma.sync GEMM (R11 config, unchanged) ---
// 288 threads: warps 0-7 consumers (2x4, 64x64 warp tiles over 128x256 CTA
// tile), warp 8 producer. BK=32, 6 stages, producer lookahead 3.
#define ROWB 80
#define A_TILEB (128 * ROWB)
#define B_TILEB (256 * ROWB)
#define STAGEB  (A_TILEB + B_TILEB)   // 30720
#define STAGES 6
#define BAR_OFF (STAGES * STAGEB)
#define SMEM_DYN (BAR_OFF + STAGES * 16)   // 184416
#define NTHR 288
#define PROD_WID 8

// GATHER: producer A-row i comes from g_x16[tok[r]] instead of Aseg + r*KD.
template <int KD, bool GATHER>
__device__ __forceinline__ void mma_mainloop(
    const __half* __restrict__ Asrc,   // GATHER ? g_x16 : Aseg (128 rows, stride KD)
    const int* __restrict__ toks,      // GATHER ? &g_tok_slot[seg+m0] : nullptr
    const __half* __restrict__ Bseg,   // 256 rows, stride KD
    char* smb, float c[4][8][4], int tid, int lane, int wid, int wm, int wn)
{
    const int NCH = KD / 32;

    uint32_t smbase = smem_u32(smb);
    uint32_t sa[STAGES], sb[STAGES];
#pragma unroll
    for (int s = 0; s < STAGES; s++) {
        sa[s] = smbase + s * STAGEB;
        sb[s] = sa[s] + A_TILEB;
    }
    uint32_t barb = smbase + BAR_OFF;   // full[s]=+s*16, empty[s]=+s*16+8

    if (tid == 0) {
#pragma unroll
        for (int s = 0; s < STAGES; s++) {
            MBARRIER_INIT(barb + s * 16, 32);       // full: producer lanes
            MBARRIER_INIT(barb + s * 16 + 8, 256);  // empty: consumer threads
        }
    }
    __syncthreads();

    if (wid == PROD_WID) {
        // ---------------- producer warp ----------------
        // Per-lane A source base pointers (16 units: u = lane + 32*i)
        const __half* aBase[16];
#pragma unroll
        for (int i = 0; i < 16; i++) {
            int u = lane + 32 * i;
            int r = u >> 2, cu = u & 3;
            if (GATHER)
                aBase[i] = Asrc + (size_t)toks[r] * HDIM + cu * 8;
            else
                aBase[i] = Asrc + (size_t)r * KD + cu * 8;
        }

        auto p_issue = [&](int ci, int s) {
            int koff = ci * 32;
#pragma unroll
            for (int i = 0; i < 16; i++) {
                int u = lane + 32 * i;
                int r = u >> 2, cu = u & 3;
                cp_async16(sa[s] + r * ROWB + cu * 16, aBase[i] + koff);
            }
#pragma unroll
            for (int i = 0; i < 32; i++) {
                int u = lane + 32 * i;
                int r = u >> 2, cu = u & 3;
                cp_async16(sb[s] + r * ROWB + cu * 16,
                           Bseg + (size_t)r * KD + koff + cu * 8);
            }
            cp_commit();
        };

        int pst = 0, pph = 1;
        for (int ci = 0; ci < NCH; ci++) {
            MBARRIER_WAIT_PARITY(barb + pst * 16 + 8, pph);
            p_issue(ci, pst);
            if (++pst == STAGES) { pst = 0; pph ^= 1; }
            if (ci >= 3) {
                cp_wait<3>();
                mbar_arrive(barb + ((ci - 3) % STAGES) * 16);
            }
        }
        cp_wait<2>();
        mbar_arrive(barb + ((NCH - 3) % STAGES) * 16);
        cp_wait<1>();
        mbar_arrive(barb + ((NCH - 2) % STAGES) * 16);
        cp_wait<0>();
        mbar_arrive(barb + ((NCH - 1) % STAGES) * 16);
    } else {
        // ---------------- consumer warps (64x64 warp tile) ----------------
        uint32_t a_off = (uint32_t)((wm * 64 + (lane & 15)) * ROWB + (lane >> 4) * 16);
        int bn = (lane & 7) + ((lane & 16) >> 1);
        uint32_t b_off = (uint32_t)((wn * 64 + bn) * ROWB + ((lane >> 3) & 1) * 16);

        int cst = 0, cph = 0;
        for (int ci = 0; ci < NCH; ci++) {
            MBARRIER_WAIT_PARITY(barb + cst * 16, cph);    // wait full
            uint32_t sav = sa[cst], sbv = sb[cst];

            uint32_t a[2][4][4], b[2][4][4];
#pragma unroll
            for (int ks = 0; ks < 2; ks++) {
#pragma unroll
                for (int mt = 0; mt < 4; mt++)
                    ldsm_x4(a[ks][mt], sav + a_off + mt * (16 * ROWB) + ks * 32);
#pragma unroll
                for (int nt = 0; nt < 4; nt++)
                    ldsm_x4(b[ks][nt], sbv + b_off + nt * (16 * ROWB) + ks * 32);
            }
            mbar_arrive(barb + cst * 16 + 8);              // release before mmas
#pragma unroll
            for (int ks = 0; ks < 2; ks++) {
#pragma unroll
                for (int mt = 0; mt < 4; mt++) {
#pragma unroll
                    for (int j = 0; j < 8; j++)
                        mma_fp16(c[mt][j], a[ks][mt],
                                 b[ks][j >> 1][(j & 1) * 2], b[ks][j >> 1][(j & 1) * 2 + 1]);
                }
            }
            if (++cst == STAGES) { cst = 0; cph ^= 1; }
        }
    }
}

__global__ void __launch_bounds__(NTHR, 1)
gemm1_mma(const float* __restrict__ b1, const float* __restrict__ w2) {
    const int e = blockIdx.z;
    const int cnt = g_count[e];
    const int m0 = blockIdx.y * 128;
    extern __shared__ char smb[];
    int tid = threadIdx.x, lane = tid & 31, wid = tid >> 5;

    if (m0 >= cnt) {
        // ---------------- idle CTA: convert a slice of w2 ----------------
        // dense idle rank across all experts
        int nt_e = 0, idle_before = 0, idle_total = 0;
#pragma unroll
        for (int ee = 0; ee < NEXP; ee++) {
            int nt = (g_count[ee] + 127) >> 7;
            if (nt > 64) nt = 64;
            if (ee == e) nt_e = nt;
            if (ee < e) idle_before += 64 - nt;
            idle_total += 64 - nt;
        }
        idle_total *= 16;
        int rank = (idle_before + ((int)blockIdx.y - nt_e)) * 16 + (int)blockIdx.x;
        // w2 tiles: 8 experts x 128 k-tiles x 32 n-tiles = 32768 tiles of 32x32
        const int TOT = 32768;
        int ti0 = (int)(((long long)rank * TOT) / idle_total);
        int ti1 = (int)(((long long)(rank + 1) * TOT) / idle_total);
        float (*tile)[33] = (float (*)[33])smb;
        int tx = tid & 31, ty = (tid >> 5) & 7;   // threads 256..287 fold onto ty 0..
        bool active = (tid < 256);
        for (int ti = ti0; ti < ti1; ti++) {
            int ee = ti >> 12;            // /4096
            int rem = ti & 4095;
            int k0 = (rem >> 5) * 32;     // 128 k-tiles
            int n0 = (rem & 31) * 32;     // 32 n-tiles
            const float* we = w2 + (size_t)ee * FDIM * HDIM;
            __half* Be = g_b2 + (size_t)ee * HDIM * FDIM;
            if (active) {
#pragma unroll
                for (int r = 0; r < 32; r += 8)
                    tile[ty + r][tx] = we[(size_t)(k0 + ty + r) * HDIM + n0 + tx];
            }
            __syncthreads();
            if (active) {
#pragma unroll
                for (int r = 0; r < 32; r += 8) {
                    int n = n0 + ty + r, k = k0 + tx;
                    Be[(size_t)n * FDIM + k] = __float2half_rn(tile[tx][ty + r]);
                }
            }
            __syncthreads();
        }
        return;
    }

    const int n0 = blockIdx.x * 256;
    int seg = 0;
    {
        int o = 0;
#pragma unroll
        for (int ee = 0; ee < NEXP; ee++) { if (ee == e) seg = o; o += g_count[ee]; }
    }
    int wm = wid & 1, wn = wid >> 1;   // consumers: wn 0..3

    const __half* Bseg = g_b1 + ((size_t)e * FDIM + n0) * HDIM;

    float c[4][8][4];
#pragma unroll
    for (int i = 0; i < 4; i++)
#pragma unroll
        for (int j = 0; j < 8; j++)
#pragma unroll
            for (int k = 0; k < 4; k++) c[i][j][k] = 0.f;

    mma_mainloop<HDIM, true>(g_x16, g_tok_slot + seg + m0, Bseg,
                             smb, c, tid, lane, wid, wm, wn);
    if (wid == PROD_WID) return;

    // epilogue: gelu(acc + b1) -> fp16 -> g_a2
    int n_base = n0 + wn * 64 + (lane & 3) * 2;
    int m_base = m0 + wm * 64 + (lane >> 2);
#pragma unroll
    for (int mt = 0; mt < 4; mt++) {
#pragma unroll
        for (int half = 0; half < 2; half++) {
            int m = m_base + mt * 16 + half * 8;
            if (m >= cnt) continue;
            __half* rowp = g_a2 + (size_t)(seg + m) * FDIM;
#pragma unroll
            for (int j = 0; j < 8; j++) {
                int n = n_base + j * 8;
                float2 bv = *(const float2*)(b1 + e * FDIM + n);
                float g0 = gelu_exact(c[mt][j][half * 2 + 0] + bv.x);
                float g1 = gelu_exact(c[mt][j][half * 2 + 1] + bv.y);
                *(__half2*)(rowp + n) = __floats2half2_rn(g0, g1);
            }
        }
    }
}

__global__ void __launch_bounds__(NTHR, 1)
gemm2_mma(const float* __restrict__ b2, float* __restrict__ out) {
    const int e = blockIdx.z;
    const int cnt = g_count[e];
    const int m0 = blockIdx.y * 128;
    if (m0 >= cnt) return;
    const int n0 = blockIdx.x * 256;
    int seg = 0;
    {
        int o = 0;
#pragma unroll
        for (int ee = 0; ee < NEXP; ee++) { if (ee == e) seg = o; o += g_count[ee]; }
    }

    extern __shared__ char smb[];
    int tid = threadIdx.x, lane = tid & 31, wid = tid >> 5;
    int wm = wid & 1, wn = wid >> 1;

    const __half* Aseg = g_a2 + (size_t)(seg + m0) * FDIM;
    const __half* Bseg = g_b2 + ((size_t)e * HDIM + n0) * FDIM;

    float c[4][8][4];
#pragma unroll
    for (int i = 0; i < 4; i++)
#pragma unroll
        for (int j = 0; j < 8; j++)
#pragma unroll
            for (int k = 0; k < 4; k++) c[i][j][k] = 0.f;

    mma_mainloop<FDIM, false>(Aseg, nullptr, Bseg, smb, c, tid, lane, wid, wm, wn);
    if (wid == PROD_WID) return;

    // epilogue: out[tok] += wt * (acc + b2)
    int n_base = n0 + wn * 64 + (lane & 3) * 2;
    int m_base = m0 + wm * 64 + (lane >> 2);
#pragma unroll
    for (int mt = 0; mt < 4; mt++) {
#pragma unroll
        for (int half = 0; half < 2; half++) {
            int m = m_base + mt * 16 + half * 8;
            if (m >= cnt) continue;
            int t = g_tok_slot[seg + m];
            float wt = g_wt_slot[seg + m];
            float* orow = out + (size_t)t * HDIM;
#pragma unroll
            for (int j = 0; j < 8; j++) {
                int n = n_base + j * 8;
                float2 bv = *(const float2*)(b2 + e * HDIM + n);
                atomicAdd(&orow[n],     wt * (c[mt][j][half * 2 + 0] + bv.x));
                atomicAdd(&orow[n + 1], wt * (c[mt][j][half * 2 + 1] + bv.y));
            }
        }
    }
}

// ---------------- launch ----------------
extern "C" void kernel_launch(void* const* d_in, const int* in_sizes, int n_in,
                              void* d_out, int out_size) {
    const float* x  = (const float*)d_in[0];
    const float* rw = (const float*)d_in[1];
    const float* rb = (const float*)d_in[2];
    const float* w1 = (const float*)d_in[3];
    const float* b1 = (const float*)d_in[4];
    const float* w2 = (const float*)d_in[5];
    const float* b2 = (const float*)d_in[6];
    float* out = (float*)d_out;

    cudaFuncSetAttribute(gemm1_mma, cudaFuncAttributeMaxDynamicSharedMemorySize, SMEM_DYN);
    cudaFuncSetAttribute(gemm2_mma, cudaFuncAttributeMaxDynamicSharedMemorySize, SMEM_DYN);

    int* cntp; cudaGetSymbolAddress((void**)&cntp, g_count);
    int* curp; cudaGetSymbolAddress((void**)&curp, g_cursor);

    cudaMemsetAsync(out, 0, (size_t)out_size * sizeof(float));
    cudaMemsetAsync(cntp, 0, NEXP * sizeof(int));
    cudaMemsetAsync(curp, 0, NEXP * sizeof(int));

    router_kernel<<<TOK / 8, dim3(32, 8)>>>(x, rw, rb);          // launch 0
    scatter_kernel<<<TOK / 256, 256>>>();                        // launch 1
    conv_w1<<<CVW1_BLKS, 256>>>(w1);                             // launch 2
    gemm1_mma<<<dim3(FDIM / 256, TOK / 128, NEXP), NTHR, SMEM_DYN>>>(b1, w2);  // launch 3
    gemm2_mma<<<dim3(HDIM / 256, TOK / 128, NEXP), NTHR, SMEM_DYN>>>(b2, out); // launch 4
}

// round 14
// speedup vs baseline: 1.3228x; 1.1311x over previous
#include <cuda_runtime.h>
#include <cuda_fp16.h>
#include <math.h>
#include <stdint.h>

// ---------------- problem constants ----------------
#define TOK   8192
#define HDIM  1024
#define NEXP  8
#define FDIM  4096
#define NSLOT (TOK*2)

// ---------------- device scratch ----------------
__device__ int   g_count[NEXP];
__device__ int   g_cursor[NEXP];
__device__ int   g_exp[TOK * 2];
__device__ float g_wt[TOK * 2];
__device__ int   g_tok_slot[NSLOT + 128];   // +128 zeroed pad for OOB tile rows
__device__ float g_wt_slot[NSLOT];

// fp16 operands. g_x16 is TOKEN-ordered (written by router); gemm1's producer
// gathers through g_tok_slot. g_a2 stays slot-ordered.
__device__ __half g_x16[(size_t)TOK * HDIM];
__device__ __half g_b1[(size_t)NEXP * FDIM * HDIM];              // [E][N][K]
__device__ __half g_a2[(size_t)(NSLOT + 128) * FDIM];
__device__ __half g_b2[(size_t)NEXP * HDIM * FDIM];              // [E][N][K]

// ---------------- helpers ----------------
__device__ __forceinline__ uint32_t smem_u32(const void* p) {
    return (uint32_t)__cvta_generic_to_shared(p);
}
__device__ __forceinline__ void cp_async16(uint32_t dst, const void* src) {
    asm volatile("cp.async.cg.shared.global [%0], [%1], 16;" :: "r"(dst), "l"(src) : "memory");
}
__device__ __forceinline__ void cp_commit() {
    asm volatile("cp.async.commit_group;" ::: "memory");
}
template <int N>
__device__ __forceinline__ void cp_wait() {
    asm volatile("cp.async.wait_group %0;" :: "n"(N) : "memory");
}
__device__ __forceinline__ void mbar_arrive(uint32_t mbar) {
    asm volatile("mbarrier.arrive.release.cta.shared::cta.b64 _, [%0];" :: "r"(mbar) : "memory");
}
#define MBARRIER_INIT(addr, cnt) \
    asm volatile("mbarrier.init.shared.b64 [%0], %1;" :: "r"(addr), "r"(cnt) : "memory")

#define MBARRIER_WAIT_PARITY(mbar_smem_addr, phase_parity) do { \
    uint32_t _mbar = (uint32_t)(mbar_smem_addr); \
    uint32_t _parity = (uint32_t)(phase_parity); \
    uint32_t _done; \
    asm volatile( \
        "{\n\t.reg .pred p;\n\t" \
        "mbarrier.try_wait.parity.acquire.cta.shared::cta.b64 p, [%1], %2;\n\t" \
        "selp.b32 %0, 1, 0, p;\n\t}" \
        : "=r"(_done) : "r"(_mbar), "r"(_parity) : "memory"); \
    if (!_done) { \
        asm volatile( \
            "{\n\t.reg .pred P1;\n\t" \
            "WAIT_LOOP_%=:\n\t" \
            "mbarrier.try_wait.parity.acquire.cta.shared::cta.b64 P1, [%0], %1, 0x989680;\n\t" \
            "@P1 bra.uni WAIT_DONE_%=;\n\t" \
            "bra.uni WAIT_LOOP_%=;\n\t" \
            "WAIT_DONE_%=:\n\t}" \
            :: "r"(_mbar), "r"(_parity) : "memory"); \
    } \
} while (0)

__device__ __forceinline__ void ldsm_x4(uint32_t* r, uint32_t addr) {
    asm volatile("ldmatrix.sync.aligned.m8n8.x4.shared.b16 {%0,%1,%2,%3}, [%4];"
                 : "=r"(r[0]), "=r"(r[1]), "=r"(r[2]), "=r"(r[3]) : "r"(addr));
}
__device__ __forceinline__ void mma_fp16(float* c, const uint32_t* a, uint32_t b0, uint32_t b1) {
    asm volatile(
        "mma.sync.aligned.m16n8k16.row.col.f32.f16.f16.f32 "
        "{%0,%1,%2,%3}, {%4,%5,%6,%7}, {%8,%9}, {%0,%1,%2,%3};"
        : "+f"(c[0]), "+f"(c[1]), "+f"(c[2]), "+f"(c[3])
        : "r"(a[0]), "r"(a[1]), "r"(a[2]), "r"(a[3]), "r"(b0), "r"(b1));
}
__device__ __forceinline__ float gelu_exact(float v) {
    return 0.5f * v * (1.0f + erff(v * 0.70710678118654752f));
}

// ---------------- router (also converts x -> fp16, token order) ----------------
__global__ void router_kernel(const float* __restrict__ x,
                              const float* __restrict__ rw,
                              const float* __restrict__ rb) {
    int t = blockIdx.x * 8 + threadIdx.y;
    if (t >= TOK) return;
    int lane = threadIdx.x;
    float acc[8];
#pragma unroll
    for (int e = 0; e < 8; e++) acc[e] = 0.f;
    const float* xr = x + (size_t)t * HDIM;
    __half* x16r = g_x16 + (size_t)t * HDIM;
    for (int h = lane; h < HDIM; h += 32) {
        float xv = xr[h];
        x16r[h] = __float2half_rn(xv);           // fused fp16 conversion
        const float4 w0 = *(const float4*)(rw + h * 8);
        const float4 w1 = *(const float4*)(rw + h * 8 + 4);
        acc[0] += xv * w0.x; acc[1] += xv * w0.y;
        acc[2] += xv * w0.z; acc[3] += xv * w0.w;
        acc[4] += xv * w1.x; acc[5] += xv * w1.y;
        acc[6] += xv * w1.z; acc[7] += xv * w1.w;
    }
#pragma unroll
    for (int off = 16; off > 0; off >>= 1)
#pragma unroll
        for (int e = 0; e < 8; e++)
            acc[e] += __shfl_down_sync(0xffffffffu, acc[e], off);
    if (lane == 0) {
        float l[8];
#pragma unroll
        for (int e = 0; e < 8; e++) l[e] = acc[e] + rb[e];
        float mx = l[0];
#pragma unroll
        for (int e = 1; e < 8; e++) mx = fmaxf(mx, l[e]);
        float p[8];
#pragma unroll
        for (int e = 0; e < 8; e++) p[e] = __expf(l[e] - mx);
        int e1 = 0; float p1 = p[0];
#pragma unroll
        for (int e = 1; e < 8; e++) if (p[e] > p1) { p1 = p[e]; e1 = e; }
        int e2 = -1; float p2 = -1.f;
#pragma unroll
        for (int e = 0; e < 8; e++) if (e != e1 && p[e] > p2) { p2 = p[e]; e2 = e; }
        float inv = 1.f / (p1 + p2);
        g_exp[t * 2 + 0] = e1; g_wt[t * 2 + 0] = p1 * inv;
        g_exp[t * 2 + 1] = e2; g_wt[t * 2 + 1] = p2 * inv;
        atomicAdd(&g_count[e1], 1);
        atomicAdd(&g_count[e2], 1);
    }
}

// scatter with inline 8-expert prefix; also zeroes the tok_slot pad
__global__ void scatter_kernel() {
    int t = blockIdx.x * blockDim.x + threadIdx.x;
    if (t < 128) g_tok_slot[NSLOT + t] = 0;
    if (t >= TOK) return;
    int offs[NEXP];
    int o = 0;
#pragma unroll
    for (int e = 0; e < NEXP; e++) { offs[e] = o; o += g_count[e]; }
#pragma unroll
    for (int k = 0; k < 2; k++) {
        int e = g_exp[t * 2 + k];
        float w = g_wt[t * 2 + k];
        int pos = atomicAdd(&g_cursor[e], 1);
        int slot = offs[e] + pos;
        g_tok_slot[slot] = t;
        g_wt_slot[slot] = w;
    }
}

// ---------------- weight conversion kernel (w1 + w2) ----------------
#define CVW1_BLKS 32768
#define CVW2_BLKS 32768
#define CONV_BLKS (CVW1_BLKS + CVW2_BLKS)

__global__ void conv_w(const float* __restrict__ w1, const float* __restrict__ w2) {
    __shared__ float tile[32][33];
    int b = blockIdx.x;
    int t = threadIdx.x;   // 256
    const float* w; __half* Bp; int K, N, idx;
    if (b < CVW1_BLKS) { w = w1; Bp = g_b1; K = HDIM; N = FDIM; idx = b; }
    else               { w = w2; Bp = g_b2; K = FDIM; N = HDIM; idx = b - CVW1_BLKS; }
    int nx = N / 32;
    int per_e = nx * (K / 32);
    int e = idx / per_e;
    int rem = idx % per_e;
    int n0 = (rem % nx) * 32, k0 = (rem / nx) * 32;
    int tx = t & 31, ty = t >> 5;
    const float* we = w + (size_t)e * K * N;
    __half* Be = Bp + (size_t)e * N * K;
#pragma unroll
    for (int r = 0; r < 32; r += 8)
        tile[ty + r][tx] = we[(size_t)(k0 + ty + r) * N + n0 + tx];
    __syncthreads();
#pragma unroll
    for (int r = 0; r < 32; r += 8) {
        int n = n0 + ty + r, k = k0 + tx;
        Be[(size_t)n * K + k] = __float2half_rn(tile[tx][ty + r]);
    }
}

// ---------------- warp-specialized mma.sync GEMM (R11 config) ----------------
// 288 threads: warps 0-7 consumers (2x4, 64x64 warp tiles over 128x256 CTA
// tile), warp 8 producer. BK=32, 6 stages, producer lookahead 3.
#define ROWB 80
#define A_TILEB (128 * ROWB)
#define B_TILEB (256 * ROWB)
#define STAGEB  (A_TILEB + B_TILEB)   // 30720
#define STAGES 6
#define BAR_OFF (STAGES * STAGEB)
#define SMEM_DYN (BAR_OFF + STAGES * 16)   // 184416
#define NTHR 288
#define PROD_WID 8

// GATHER: producer A-row r comes from g_x16[toks[r]] instead of Asrc + r*KD.
template <int KD, bool GATHER>
__device__ __forceinline__ void mma_mainloop(
    const __half* __restrict__ Asrc,
    const int* __restrict__ toks,
    const __half* __restrict__ Bseg,   // 256 rows, stride KD
    char* smb, float c[4][8][4], int tid, int lane, int wid, int wm, int wn)
{
    const int NCH = KD / 32;

    uint32_t smbase = smem_u32(smb);
    uint32_t sa[STAGES], sb[STAGES];
#pragma unroll
    for (int s = 0; s < STAGES; s++) {
        sa[s] = smbase + s * STAGEB;
        sb[s] = sa[s] + A_TILEB;
    }
    uint32_t barb = smbase + BAR_OFF;   // full[s]=+s*16, empty[s]=+s*16+8

    if (tid == 0) {
#pragma unroll
        for (int s = 0; s < STAGES; s++) {
            MBARRIER_INIT(barb + s * 16, 32);       // full: producer lanes
            MBARRIER_INIT(barb + s * 16 + 8, 256);  // empty: consumer threads
        }
    }
    __syncthreads();

    if (wid == PROD_WID) {
        // ---------------- producer warp ----------------
        const __half* aBase[16];
#pragma unroll
        for (int i = 0; i < 16; i++) {
            int u = lane + 32 * i;
            int r = u >> 2, cu = u & 3;
            if (GATHER)
                aBase[i] = Asrc + (size_t)toks[r] * HDIM + cu * 8;
            else
                aBase[i] = Asrc + (size_t)r * KD + cu * 8;
        }

        auto p_issue = [&](int ci, int s) {
            int koff = ci * 32;
#pragma unroll
            for (int i = 0; i < 16; i++) {
                int u = lane + 32 * i;
                int r = u >> 2, cu = u & 3;
                cp_async16(sa[s] + r * ROWB + cu * 16, aBase[i] + koff);
            }
#pragma unroll
            for (int i = 0; i < 32; i++) {
                int u = lane + 32 * i;
                int r = u >> 2, cu = u & 3;
                cp_async16(sb[s] + r * ROWB + cu * 16,
                           Bseg + (size_t)r * KD + koff + cu * 8);
            }
            cp_commit();
        };

        int pst = 0, pph = 1;
        for (int ci = 0; ci < NCH; ci++) {
            MBARRIER_WAIT_PARITY(barb + pst * 16 + 8, pph);
            p_issue(ci, pst);
            if (++pst == STAGES) { pst = 0; pph ^= 1; }
            if (ci >= 3) {
                cp_wait<3>();
                mbar_arrive(barb + ((ci - 3) % STAGES) * 16);
            }
        }
        cp_wait<2>();
        mbar_arrive(barb + ((NCH - 3) % STAGES) * 16);
        cp_wait<1>();
        mbar_arrive(barb + ((NCH - 2) % STAGES) * 16);
        cp_wait<0>();
        mbar_arrive(barb + ((NCH - 1) % STAGES) * 16);
    } else {
        // ---------------- consumer warps (64x64 warp tile) ----------------
        uint32_t a_off = (uint32_t)((wm * 64 + (lane & 15)) * ROWB + (lane >> 4) * 16);
        int bn = (lane & 7) + ((lane & 16) >> 1);
        uint32_t b_off = (uint32_t)((wn * 64 + bn) * ROWB + ((lane >> 3) & 1) * 16);

        int cst = 0, cph = 0;
        for (int ci = 0; ci < NCH; ci++) {
            MBARRIER_WAIT_PARITY(barb + cst * 16, cph);    // wait full
            uint32_t sav = sa[cst], sbv = sb[cst];

            uint32_t a[2][4][4], b[2][4][4];
#pragma unroll
            for (int ks = 0; ks < 2; ks++) {
#pragma unroll
                for (int mt = 0; mt < 4; mt++)
                    ldsm_x4(a[ks][mt], sav + a_off + mt * (16 * ROWB) + ks * 32);
#pragma unroll
                for (int nt = 0; nt < 4; nt++)
                    ldsm_x4(b[ks][nt], sbv + b_off + nt * (16 * ROWB) + ks * 32);
            }
            mbar_arrive(barb + cst * 16 + 8);              // release before mmas
#pragma unroll
            for (int ks = 0; ks < 2; ks++) {
#pragma unroll
                for (int mt = 0; mt < 4; mt++) {
#pragma unroll
                    for (int j = 0; j < 8; j++)
                        mma_fp16(c[mt][j], a[ks][mt],
                                 b[ks][j >> 1][(j & 1) * 2], b[ks][j >> 1][(j & 1) * 2 + 1]);
                }
            }
            if (++cst == STAGES) { cst = 0; cph ^= 1; }
        }
    }
}

__global__ void __launch_bounds__(NTHR, 1)
gemm1_mma(const float* __restrict__ b1) {
    const int e = blockIdx.z;
    const int cnt = g_count[e];
    const int m0 = blockIdx.y * 128;
    if (m0 >= cnt) return;
    const int n0 = blockIdx.x * 256;
    int seg = 0;
    {
        int o = 0;
#pragma unroll
        for (int ee = 0; ee < NEXP; ee++) { if (ee == e) seg = o; o += g_count[ee]; }
    }

    extern __shared__ char smb[];
    int tid = threadIdx.x, lane = tid & 31, wid = tid >> 5;
    int wm = wid & 1, wn = wid >> 1;   // consumers: wn 0..3

    const __half* Bseg = g_b1 + ((size_t)e * FDIM + n0) * HDIM;

    float c[4][8][4];
#pragma unroll
    for (int i = 0; i < 4; i++)
#pragma unroll
        for (int j = 0; j < 8; j++)
#pragma unroll
            for (int k = 0; k < 4; k++) c[i][j][k] = 0.f;

    mma_mainloop<HDIM, true>(g_x16, g_tok_slot + seg + m0, Bseg,
                             smb, c, tid, lane, wid, wm, wn);
    if (wid == PROD_WID) return;

    // epilogue: gelu(acc + b1) -> fp16 -> g_a2
    int n_base = n0 + wn * 64 + (lane & 3) * 2;
    int m_base = m0 + wm * 64 + (lane >> 2);
#pragma unroll
    for (int mt = 0; mt < 4; mt++) {
#pragma unroll
        for (int half = 0; half < 2; half++) {
            int m = m_base + mt * 16 + half * 8;
            if (m >= cnt) continue;
            __half* rowp = g_a2 + (size_t)(seg + m) * FDIM;
#pragma unroll
            for (int j = 0; j < 8; j++) {
                int n = n_base + j * 8;
                float2 bv = *(const float2*)(b1 + e * FDIM + n);
                float g0 = gelu_exact(c[mt][j][half * 2 + 0] + bv.x);
                float g1 = gelu_exact(c[mt][j][half * 2 + 1] + bv.y);
                *(__half2*)(rowp + n) = __floats2half2_rn(g0, g1);
            }
        }
    }
}

__global__ void __launch_bounds__(NTHR, 1)
gemm2_mma(const float* __restrict__ b2, float* __restrict__ out) {
    const int e = blockIdx.z;
    const int cnt = g_count[e];
    const int m0 = blockIdx.y * 128;
    if (m0 >= cnt) return;
    const int n0 = blockIdx.x * 256;
    int seg = 0;
    {
        int o = 0;
#pragma unroll
        for (int ee = 0; ee < NEXP; ee++) { if (ee == e) seg = o; o += g_count[ee]; }
    }

    extern __shared__ char smb[];
    int tid = threadIdx.x, lane = tid & 31, wid = tid >> 5;
    int wm = wid & 1, wn = wid >> 1;

    const __half* Aseg = g_a2 + (size_t)(seg + m0) * FDIM;
    const __half* Bseg = g_b2 + ((size_t)e * HDIM + n0) * FDIM;

    float c[4][8][4];
#pragma unroll
    for (int i = 0; i < 4; i++)
#pragma unroll
        for (int j = 0; j < 8; j++)
#pragma unroll
            for (int k = 0; k < 4; k++) c[i][j][k] = 0.f;

    mma_mainloop<FDIM, false>(Aseg, nullptr, Bseg, smb, c, tid, lane, wid, wm, wn);
    if (wid == PROD_WID) return;

    // epilogue: out[tok] += wt * (acc + b2)
    int n_base = n0 + wn * 64 + (lane & 3) * 2;
    int m_base = m0 + wm * 64 + (lane >> 2);
#pragma unroll
    for (int mt = 0; mt < 4; mt++) {
#pragma unroll
        for (int half = 0; half < 2; half++) {
            int m = m_base + mt * 16 + half * 8;
            if (m >= cnt) continue;
            int t = g_tok_slot[seg + m];
            float wt = g_wt_slot[seg + m];
            float* orow = out + (size_t)t * HDIM;
#pragma unroll
            for (int j = 0; j < 8; j++) {
                int n = n_base + j * 8;
                float2 bv = *(const float2*)(b2 + e * HDIM + n);
                atomicAdd(&orow[n],     wt * (c[mt][j][half * 2 + 0] + bv.x));
                atomicAdd(&orow[n + 1], wt * (c[mt][j][half * 2 + 1] + bv.y));
            }
        }
    }
}

// ---------------- launch ----------------
extern "C" void kernel_launch(void* const* d_in, const int* in_sizes, int n_in,
                              void* d_out, int out_size) {
    const float* x  = (const float*)d_in[0];
    const float* rw = (const float*)d_in[1];
    const float* rb = (const float*)d_in[2];
    const float* w1 = (const float*)d_in[3];
    const float* b1 = (const float*)d_in[4];
    const float* w2 = (const float*)d_in[5];
    const float* b2 = (const float*)d_in[6];
    float* out = (float*)d_out;

    cudaFuncSetAttribute(gemm1_mma, cudaFuncAttributeMaxDynamicSharedMemorySize, SMEM_DYN);
    cudaFuncSetAttribute(gemm2_mma, cudaFuncAttributeMaxDynamicSharedMemorySize, SMEM_DYN);

    int* cntp; cudaGetSymbolAddress((void**)&cntp, g_count);
    int* curp; cudaGetSymbolAddress((void**)&curp, g_cursor);

    cudaMemsetAsync(out, 0, (size_t)out_size * sizeof(float));
    cudaMemsetAsync(cntp, 0, NEXP * sizeof(int));
    cudaMemsetAsync(curp, 0, NEXP * sizeof(int));

    router_kernel<<<TOK / 8, dim3(32, 8)>>>(x, rw, rb);          // launch 0
    scatter_kernel<<<TOK / 256, 256>>>();                        // launch 1
    conv_w<<<CONV_BLKS, 256>>>(w1, w2);                          // launch 2
    gemm1_mma<<<dim3(FDIM / 256, TOK / 128, NEXP), NTHR, SMEM_DYN>>>(b1);       // launch 3
    gemm2_mma<<<dim3(HDIM / 256, TOK / 128, NEXP), NTHR, SMEM_DYN>>>(b2, out);  // launch 4
}

// round 15
// speedup vs baseline: 1.3530x; 1.0229x over previous
#include <cuda_runtime.h>
#include <cuda_fp16.h>
#include <math.h>
#include <stdint.h>

// ---------------- problem constants ----------------
#define TOK   8192
#define HDIM  1024
#define NEXP  8
#define FDIM  4096
#define NSLOT (TOK*2)

// ---------------- device scratch ----------------
__device__ int   g_count[NEXP];
__device__ int   g_cursor[NEXP];
__device__ int   g_exp[TOK * 2];
__device__ float g_wt[TOK * 2];
__device__ int   g_tok_slot[NSLOT + 128];   // +128 zeroed pad for OOB tile rows
__device__ float g_wt_slot[NSLOT];

// fp16 operands. g_x16 is TOKEN-ordered (written by router); gemm1's producer
// gathers through g_tok_slot. g_a2 stays slot-ordered.
__device__ __half g_x16[(size_t)TOK * HDIM];
__device__ __half g_b1[(size_t)NEXP * FDIM * HDIM];              // [E][N][K]
__device__ __half g_a2[(size_t)(NSLOT + 128) * FDIM];
__device__ __half g_b2[(size_t)NEXP * HDIM * FDIM];              // [E][N][K]

// ---------------- helpers ----------------
__device__ __forceinline__ uint32_t smem_u32(const void* p) {
    return (uint32_t)__cvta_generic_to_shared(p);
}
__device__ __forceinline__ void cp_async16(uint32_t dst, const void* src) {
    asm volatile("cp.async.cg.shared.global [%0], [%1], 16;" :: "r"(dst), "l"(src) : "memory");
}
__device__ __forceinline__ void cp_commit() {
    asm volatile("cp.async.commit_group;" ::: "memory");
}
template <int N>
__device__ __forceinline__ void cp_wait() {
    asm volatile("cp.async.wait_group %0;" :: "n"(N) : "memory");
}
__device__ __forceinline__ void mbar_arrive(uint32_t mbar) {
    asm volatile("mbarrier.arrive.release.cta.shared::cta.b64 _, [%0];" :: "r"(mbar) : "memory");
}
#define MBARRIER_INIT(addr, cnt) \
    asm volatile("mbarrier.init.shared.b64 [%0], %1;" :: "r"(addr), "r"(cnt) : "memory")

#define MBARRIER_WAIT_PARITY(mbar_smem_addr, phase_parity) do { \
    uint32_t _mbar = (uint32_t)(mbar_smem_addr); \
    uint32_t _parity = (uint32_t)(phase_parity); \
    uint32_t _done; \
    asm volatile( \
        "{\n\t.reg .pred p;\n\t" \
        "mbarrier.try_wait.parity.acquire.cta.shared::cta.b64 p, [%1], %2;\n\t" \
        "selp.b32 %0, 1, 0, p;\n\t}" \
        : "=r"(_done) : "r"(_mbar), "r"(_parity) : "memory"); \
    if (!_done) { \
        asm volatile( \
            "{\n\t.reg .pred P1;\n\t" \
            "WAIT_LOOP_%=:\n\t" \
            "mbarrier.try_wait.parity.acquire.cta.shared::cta.b64 P1, [%0], %1, 0x989680;\n\t" \
            "@P1 bra.uni WAIT_DONE_%=;\n\t" \
            "bra.uni WAIT_LOOP_%=;\n\t" \
            "WAIT_DONE_%=:\n\t}" \
            :: "r"(_mbar), "r"(_parity) : "memory"); \
    } \
} while (0)

__device__ __forceinline__ void ldsm_x4(uint32_t* r, uint32_t addr) {
    asm volatile("ldmatrix.sync.aligned.m8n8.x4.shared.b16 {%0,%1,%2,%3}, [%4];"
                 : "=r"(r[0]), "=r"(r[1]), "=r"(r[2]), "=r"(r[3]) : "r"(addr));
}
__device__ __forceinline__ void mma_fp16(float* c, const uint32_t* a, uint32_t b0, uint32_t b1) {
    asm volatile(
        "mma.sync.aligned.m16n8k16.row.col.f32.f16.f16.f32 "
        "{%0,%1,%2,%3}, {%4,%5,%6,%7}, {%8,%9}, {%0,%1,%2,%3};"
        : "+f"(c[0]), "+f"(c[1]), "+f"(c[2]), "+f"(c[3])
        : "r"(a[0]), "r"(a[1]), "r"(a[2]), "r"(a[3]), "r"(b0), "r"(b1));
}
__device__ __forceinline__ float gelu_exact(float v) {
    return 0.5f * v * (1.0f + erff(v * 0.70710678118654752f));
}

// ---------------- router (also converts x -> fp16, token order) ----------------
__global__ void router_kernel(const float* __restrict__ x,
                              const float* __restrict__ rw,
                              const float* __restrict__ rb) {
    int t = blockIdx.x * 8 + threadIdx.y;
    if (t >= TOK) return;
    int lane = threadIdx.x;
    float acc[8];
#pragma unroll
    for (int e = 0; e < 8; e++) acc[e] = 0.f;
    const float* xr = x + (size_t)t * HDIM;
    __half* x16r = g_x16 + (size_t)t * HDIM;
    for (int h = lane; h < HDIM; h += 32) {
        float xv = xr[h];
        x16r[h] = __float2half_rn(xv);           // fused fp16 conversion
        const float4 w0 = *(const float4*)(rw + h * 8);
        const float4 w1 = *(const float4*)(rw + h * 8 + 4);
        acc[0] += xv * w0.x; acc[1] += xv * w0.y;
        acc[2] += xv * w0.z; acc[3] += xv * w0.w;
        acc[4] += xv * w1.x; acc[5] += xv * w1.y;
        acc[6] += xv * w1.z; acc[7] += xv * w1.w;
    }
#pragma unroll
    for (int off = 16; off > 0; off >>= 1)
#pragma unroll
        for (int e = 0; e < 8; e++)
            acc[e] += __shfl_down_sync(0xffffffffu, acc[e], off);
    if (lane == 0) {
        float l[8];
#pragma unroll
        for (int e = 0; e < 8; e++) l[e] = acc[e] + rb[e];
        float mx = l[0];
#pragma unroll
        for (int e = 1; e < 8; e++) mx = fmaxf(mx, l[e]);
        float p[8];
#pragma unroll
        for (int e = 0; e < 8; e++) p[e] = __expf(l[e] - mx);
        int e1 = 0; float p1 = p[0];
#pragma unroll
        for (int e = 1; e < 8; e++) if (p[e] > p1) { p1 = p[e]; e1 = e; }
        int e2 = -1; float p2 = -1.f;
#pragma unroll
        for (int e = 0; e < 8; e++) if (e != e1 && p[e] > p2) { p2 = p[e]; e2 = e; }
        float inv = 1.f / (p1 + p2);
        g_exp[t * 2 + 0] = e1; g_wt[t * 2 + 0] = p1 * inv;
        g_exp[t * 2 + 1] = e2; g_wt[t * 2 + 1] = p2 * inv;
        atomicAdd(&g_count[e1], 1);
        atomicAdd(&g_count[e2], 1);
    }
}

// ---------------- fused conv (64x64 tiles, vectorized) + scatter ----------------
// w1: 8 experts x (1024/64 k) x (4096/64 n) = 8192 tiles
// w2: 8 experts x (4096/64 k) x (1024/64 n) = 8192 tiles
// +32 scatter blocks at the tail.
#define CVW1_BLKS 8192
#define CVW2_BLKS 8192
#define SCAT_BLKS 32
#define CONV_BLKS (CVW1_BLKS + CVW2_BLKS + SCAT_BLKS)

__global__ void conv_scatter(const float* __restrict__ w1, const float* __restrict__ w2) {
    __shared__ float tile[64][65];
    int b = blockIdx.x;
    int t = threadIdx.x;   // 256

    if (b >= CVW1_BLKS + CVW2_BLKS) {
        // ---- scatter (with inline 8-expert prefix) ----
        int tok = (b - CVW1_BLKS - CVW2_BLKS) * 256 + t;
        if (tok < 128) g_tok_slot[NSLOT + tok] = 0;
        if (tok >= TOK) return;
        int offs[NEXP];
        int o = 0;
#pragma unroll
        for (int e = 0; e < NEXP; e++) { offs[e] = o; o += g_count[e]; }
#pragma unroll
        for (int k = 0; k < 2; k++) {
            int e = g_exp[tok * 2 + k];
            float w = g_wt[tok * 2 + k];
            int pos = atomicAdd(&g_cursor[e], 1);
            int slot = offs[e] + pos;
            g_tok_slot[slot] = tok;
            g_wt_slot[slot] = w;
        }
        return;
    }

    const float* w; __half* Bp; int K, N, idx;
    if (b < CVW1_BLKS) { w = w1; Bp = g_b1; K = HDIM; N = FDIM; idx = b; }
    else               { w = w2; Bp = g_b2; K = FDIM; N = HDIM; idx = b - CVW1_BLKS; }
    int nx = N / 64;
    int per_e = nx * (K / 64);
    int e = idx / per_e;
    int rem = idx % per_e;
    int n0 = (rem % nx) * 64, k0 = (rem / nx) * 64;
    const float* we = w + (size_t)e * K * N + n0;
    __half* Be = Bp + (size_t)e * N * K + k0;

    // load 64x64 floats: thread -> (row = t>>4 (+16 per pass), c4 = t&15)
    int lr = t >> 4, lc = (t & 15) * 4;
#pragma unroll
    for (int pass = 0; pass < 4; pass++) {
        int k = lr + pass * 16;
        float4 v = *(const float4*)(we + (size_t)(k0 + k) * N + lc);
        tile[k][lc] = v.x; tile[k][lc + 1] = v.y;
        tile[k][lc + 2] = v.z; tile[k][lc + 3] = v.w;
    }
    __syncthreads();

    // store transposed: thread -> (n = t>>2, kblk = (t&3)*16), 2x uint4 (16 halves)
    int n = t >> 2, kb = (t & 3) * 16;
    __half hv[16];
#pragma unroll
    for (int i = 0; i < 16; i++)
        hv[i] = __float2half_rn(tile[kb + i][n]);
    *(uint4*)(Be + (size_t)(n0 + n) * K + kb)     = *(uint4*)&hv[0];
    *(uint4*)(Be + (size_t)(n0 + n) * K + kb + 8) = *(uint4*)&hv[8];
}

// ---------------- warp-specialized mma.sync GEMM (R11 config, FROZEN) -------
#define ROWB 80
#define A_TILEB (128 * ROWB)
#define B_TILEB (256 * ROWB)
#define STAGEB  (A_TILEB + B_TILEB)   // 30720
#define STAGES 6
#define BAR_OFF (STAGES * STAGEB)
#define SMEM_DYN (BAR_OFF + STAGES * 16)   // 184416
#define NTHR 288
#define PROD_WID 8

// GATHER: producer A-row r comes from g_x16[toks[r]] instead of Asrc + r*KD.
template <int KD, bool GATHER>
__device__ __forceinline__ void mma_mainloop(
    const __half* __restrict__ Asrc,
    const int* __restrict__ toks,
    const __half* __restrict__ Bseg,   // 256 rows, stride KD
    char* smb, float c[4][8][4], int tid, int lane, int wid, int wm, int wn)
{
    const int NCH = KD / 32;

    uint32_t smbase = smem_u32(smb);
    uint32_t sa[STAGES], sb[STAGES];
#pragma unroll
    for (int s = 0; s < STAGES; s++) {
        sa[s] = smbase + s * STAGEB;
        sb[s] = sa[s] + A_TILEB;
    }
    uint32_t barb = smbase + BAR_OFF;   // full[s]=+s*16, empty[s]=+s*16+8

    if (tid == 0) {
#pragma unroll
        for (int s = 0; s < STAGES; s++) {
            MBARRIER_INIT(barb + s * 16, 32);       // full: producer lanes
            MBARRIER_INIT(barb + s * 16 + 8, 256);  // empty: consumer threads
        }
    }
    __syncthreads();

    if (wid == PROD_WID) {
        // ---------------- producer warp ----------------
        const __half* aBase[16];
#pragma unroll
        for (int i = 0; i < 16; i++) {
            int u = lane + 32 * i;
            int r = u >> 2, cu = u & 3;
            if (GATHER)
                aBase[i] = Asrc + (size_t)toks[r] * HDIM + cu * 8;
            else
                aBase[i] = Asrc + (size_t)r * KD + cu * 8;
        }

        auto p_issue = [&](int ci, int s) {
            int koff = ci * 32;
#pragma unroll
            for (int i = 0; i < 16; i++) {
                int u = lane + 32 * i;
                int r = u >> 2, cu = u & 3;
                cp_async16(sa[s] + r * ROWB + cu * 16, aBase[i] + koff);
            }
#pragma unroll
            for (int i = 0; i < 32; i++) {
                int u = lane + 32 * i;
                int r = u >> 2, cu = u & 3;
                cp_async16(sb[s] + r * ROWB + cu * 16,
                           Bseg + (size_t)r * KD + koff + cu * 8);
            }
            cp_commit();
        };

        int pst = 0, pph = 1;
        for (int ci = 0; ci < NCH; ci++) {
            MBARRIER_WAIT_PARITY(barb + pst * 16 + 8, pph);
            p_issue(ci, pst);
            if (++pst == STAGES) { pst = 0; pph ^= 1; }
            if (ci >= 3) {
                cp_wait<3>();
                mbar_arrive(barb + ((ci - 3) % STAGES) * 16);
            }
        }
        cp_wait<2>();
        mbar_arrive(barb + ((NCH - 3) % STAGES) * 16);
        cp_wait<1>();
        mbar_arrive(barb + ((NCH - 2) % STAGES) * 16);
        cp_wait<0>();
        mbar_arrive(barb + ((NCH - 1) % STAGES) * 16);
    } else {
        // ---------------- consumer warps (64x64 warp tile) ----------------
        uint32_t a_off = (uint32_t)((wm * 64 + (lane & 15)) * ROWB + (lane >> 4) * 16);
        int bn = (lane & 7) + ((lane & 16) >> 1);
        uint32_t b_off = (uint32_t)((wn * 64 + bn) * ROWB + ((lane >> 3) & 1) * 16);

        int cst = 0, cph = 0;
        for (int ci = 0; ci < NCH; ci++) {
            MBARRIER_WAIT_PARITY(barb + cst * 16, cph);    // wait full
            uint32_t sav = sa[cst], sbv = sb[cst];

            uint32_t a[2][4][4], b[2][4][4];
#pragma unroll
            for (int ks = 0; ks < 2; ks++) {
#pragma unroll
                for (int mt = 0; mt < 4; mt++)
                    ldsm_x4(a[ks][mt], sav + a_off + mt * (16 * ROWB) + ks * 32);
#pragma unroll
                for (int nt = 0; nt < 4; nt++)
                    ldsm_x4(b[ks][nt], sbv + b_off + nt * (16 * ROWB) + ks * 32);
            }
            mbar_arrive(barb + cst * 16 + 8);              // release before mmas
#pragma unroll
            for (int ks = 0; ks < 2; ks++) {
#pragma unroll
                for (int mt = 0; mt < 4; mt++) {
#pragma unroll
                    for (int j = 0; j < 8; j++)
                        mma_fp16(c[mt][j], a[ks][mt],
                                 b[ks][j >> 1][(j & 1) * 2], b[ks][j >> 1][(j & 1) * 2 + 1]);
                }
            }
            if (++cst == STAGES) { cst = 0; cph ^= 1; }
        }
    }
}

__global__ void __launch_bounds__(NTHR, 1)
gemm1_mma(const float* __restrict__ b1) {
    const int e = blockIdx.z;
    const int cnt = g_count[e];
    const int m0 = blockIdx.y * 128;
    if (m0 >= cnt) return;
    const int n0 = blockIdx.x * 256;
    int seg = 0;
    {
        int o = 0;
#pragma unroll
        for (int ee = 0; ee < NEXP; ee++) { if (ee == e) seg = o; o += g_count[ee]; }
    }

    extern __shared__ char smb[];
    int tid = threadIdx.x, lane = tid & 31, wid = tid >> 5;
    int wm = wid & 1, wn = wid >> 1;   // consumers: wn 0..3

    const __half* Bseg = g_b1 + ((size_t)e * FDIM + n0) * HDIM;

    float c[4][8][4];
#pragma unroll
    for (int i = 0; i < 4; i++)
#pragma unroll
        for (int j = 0; j < 8; j++)
#pragma unroll
            for (int k = 0; k < 4; k++) c[i][j][k] = 0.f;

    mma_mainloop<HDIM, true>(g_x16, g_tok_slot + seg + m0, Bseg,
                             smb, c, tid, lane, wid, wm, wn);
    if (wid == PROD_WID) return;

    // epilogue: gelu(acc + b1) -> fp16 -> g_a2
    int n_base = n0 + wn * 64 + (lane & 3) * 2;
    int m_base = m0 + wm * 64 + (lane >> 2);
#pragma unroll
    for (int mt = 0; mt < 4; mt++) {
#pragma unroll
        for (int half = 0; half < 2; half++) {
            int m = m_base + mt * 16 + half * 8;
            if (m >= cnt) continue;
            __half* rowp = g_a2 + (size_t)(seg + m) * FDIM;
#pragma unroll
            for (int j = 0; j < 8; j++) {
                int n = n_base + j * 8;
                float2 bv = *(const float2*)(b1 + e * FDIM + n);
                float g0 = gelu_exact(c[mt][j][half * 2 + 0] + bv.x);
                float g1 = gelu_exact(c[mt][j][half * 2 + 1] + bv.y);
                *(__half2*)(rowp + n) = __floats2half2_rn(g0, g1);
            }
        }
    }
}

__global__ void __launch_bounds__(NTHR, 1)
gemm2_mma(const float* __restrict__ b2, float* __restrict__ out) {
    const int e = blockIdx.z;
    const int cnt = g_count[e];
    const int m0 = blockIdx.y * 128;
    if (m0 >= cnt) return;
    const int n0 = blockIdx.x * 256;
    int seg = 0;
    {
        int o = 0;
#pragma unroll
        for (int ee = 0; ee < NEXP; ee++) { if (ee == e) seg = o; o += g_count[ee]; }
    }

    extern __shared__ char smb[];
    int tid = threadIdx.x, lane = tid & 31, wid = tid >> 5;
    int wm = wid & 1, wn = wid >> 1;

    const __half* Aseg = g_a2 + (size_t)(seg + m0) * FDIM;
    const __half* Bseg = g_b2 + ((size_t)e * HDIM + n0) * FDIM;

    float c[4][8][4];
#pragma unroll
    for (int i = 0; i < 4; i++)
#pragma unroll
        for (int j = 0; j < 8; j++)
#pragma unroll
            for (int k = 0; k < 4; k++) c[i][j][k] = 0.f;

    mma_mainloop<FDIM, false>(Aseg, nullptr, Bseg, smb, c, tid, lane, wid, wm, wn);
    if (wid == PROD_WID) return;

    // epilogue: out[tok] += wt * (acc + b2)
    int n_base = n0 + wn * 64 + (lane & 3) * 2;
    int m_base = m0 + wm * 64 + (lane >> 2);
#pragma unroll
    for (int mt = 0; mt < 4; mt++) {
#pragma unroll
        for (int half = 0; half < 2; half++) {
            int m = m_base + mt * 16 + half * 8;
            if (m >= cnt) continue;
            int t = g_tok_slot[seg + m];
            float wt = g_wt_slot[seg + m];
            float* orow = out + (size_t)t * HDIM;
#pragma unroll
            for (int j = 0; j < 8; j++) {
                int n = n_base + j * 8;
                float2 bv = *(const float2*)(b2 + e * HDIM + n);
                atomicAdd(&orow[n],     wt * (c[mt][j][half * 2 + 0] + bv.x));
                atomicAdd(&orow[n + 1], wt * (c[mt][j][half * 2 + 1] + bv.y));
            }
        }
    }
}

// ---------------- launch ----------------
extern "C" void kernel_launch(void* const* d_in, const int* in_sizes, int n_in,
                              void* d_out, int out_size) {
    const float* x  = (const float*)d_in[0];
    const float* rw = (const float*)d_in[1];
    const float* rb = (const float*)d_in[2];
    const float* w1 = (const float*)d_in[3];
    const float* b1 = (const float*)d_in[4];
    const float* w2 = (const float*)d_in[5];
    const float* b2 = (const float*)d_in[6];
    float* out = (float*)d_out;

    cudaFuncSetAttribute(gemm1_mma, cudaFuncAttributeMaxDynamicSharedMemorySize, SMEM_DYN);
    cudaFuncSetAttribute(gemm2_mma, cudaFuncAttributeMaxDynamicSharedMemorySize, SMEM_DYN);

    int* cntp; cudaGetSymbolAddress((void**)&cntp, g_count);
    int* curp; cudaGetSymbolAddress((void**)&curp, g_cursor);

    cudaMemsetAsync(out, 0, (size_t)out_size * sizeof(float));
    cudaMemsetAsync(cntp, 0, NEXP * sizeof(int));
    cudaMemsetAsync(curp, 0, NEXP * sizeof(int));

    router_kernel<<<TOK / 8, dim3(32, 8)>>>(x, rw, rb);          // launch 0
    conv_scatter<<<CONV_BLKS, 256>>>(w1, w2);                    // launch 1
    gemm1_mma<<<dim3(FDIM / 256, TOK / 128, NEXP), NTHR, SMEM_DYN>>>(b1);       // launch 2
    gemm2_mma<<<dim3(HDIM / 256, TOK / 128, NEXP), NTHR, SMEM_DYN>>>(b2, out);  // launch 3 (profiled)
}